// round 1
// baseline (speedup 1.0000x reference)
#include <cuda_runtime.h>
#include <math.h>

#define NN 16000
#define EE 256000
#define EP (EE+NN)
#define DIN 1280
#define HD 256
#define GG 32
#define OO 64

// ---------------- device scratch (static, allocation-free) ----------------
__device__ float d_h0[NN*HD];
__device__ float d_h1[NN*HD];
__device__ float d_xl[NN*HD];
__device__ float d_xr[NN*HD];
__device__ int   d_degGat[NN], d_degGin[NN];
__device__ int   d_ptrGat[NN+1], d_ptrGin[NN+1];
__device__ int   d_curGat[NN], d_curGin[NN];
__device__ int   d_colGat[EP], d_colGin[EE];
__device__ float d_red[4];
__device__ float d_gate[NN], d_gmax[GG], d_gsum[GG], d_emb[GG*HD];

__device__ __forceinline__ void atomicMaxF(float* addr, float v){
  if (v >= 0.f) atomicMax((int*)addr, __float_as_int(v));
  else          atomicMin((unsigned int*)addr, __float_as_uint(v));
}

// ---------------- init + CSR build ----------------
__global__ void init_kernel(int* degGat,int* degGin,float* red,float* gmax,float* gsum,float* emb){
  int i = blockIdx.x*blockDim.x+threadIdx.x;
  if (i < NN){ degGat[i]=0; degGin[i]=0; }
  if (i < 4)  red[i]=0.f;
  if (i < GG){ gmax[i]=-1e30f; gsum[i]=0.f; }
  if (i < GG*HD) emb[i]=0.f;
}

__global__ void hist_kernel(const int* __restrict__ ei, int* degGat, int* degGin){
  int e = blockIdx.x*blockDim.x+threadIdx.x;
  if (e >= EP) return;
  if (e < EE){
    int d = ei[EE+e];
    atomicAdd(&degGat[d],1);
    atomicAdd(&degGin[d],1);
  } else {
    atomicAdd(&degGat[e-EE],1);
  }
}

__global__ void scan_kernel(const int* __restrict__ deg, int* indptr, int* cursor){
  __shared__ int sh[1024];
  int t = threadIdx.x;
  const int CH = (NN+1023)/1024;   // 16
  int st = t*CH;
  int sum = 0;
  for (int i=0;i<CH;i++){ int idx=st+i; if (idx<NN) sum += deg[idx]; }
  sh[t]=sum; __syncthreads();
  for (int off=1; off<1024; off<<=1){
    int add = (t>=off)? sh[t-off] : 0;
    __syncthreads();
    sh[t]+=add;
    __syncthreads();
  }
  int run = (t==0)? 0 : sh[t-1];
  for (int i=0;i<CH;i++){
    int idx=st+i;
    if (idx<NN){ indptr[idx]=run; cursor[idx]=run; run+=deg[idx]; }
  }
  if (t==1023) indptr[NN]=sh[1023];
}

__global__ void fill_kernel(const int* __restrict__ ei, int* curGat, int* colGat, int* curGin, int* colGin){
  int e = blockIdx.x*blockDim.x+threadIdx.x;
  if (e >= EP) return;
  if (e < EE){
    int s = ei[e], d = ei[EE+e];
    colGat[atomicAdd(&curGat[d],1)] = s;
    colGin[atomicAdd(&curGin[d],1)] = s;
  } else {
    int v = e-EE;
    colGat[atomicAdd(&curGat[v],1)] = v;
  }
}

// ---------------- fused GEMM: C[M,256] = A[M,K] @ B[K,256] + epilogue ----------------
enum { EPI_BIAS=0, EPI_RELU_BN=1, EPI_GIN=2, EPI_RES=3, EPI_TANH=4 };

template<int EPI>
__global__ __launch_bounds__(256)
void gemm_kernel(const float* __restrict__ A, const float* __restrict__ B,
                 const float* __restrict__ bias,
                 const float* __restrict__ g,   const float* __restrict__ be,
                 const float* __restrict__ lng, const float* __restrict__ lnb,
                 const float* __restrict__ hres,
                 const float* __restrict__ stats,
                 float* __restrict__ C, int K)
{
  __shared__ float As[16][128];
  __shared__ float Bs[16][64];
  int tid = threadIdx.x;
  int tx = tid & 15, ty = tid >> 4;
  int m0 = blockIdx.x * 128;
  int n0 = blockIdx.y * 64;
  float acc[8][4];
  #pragma unroll
  for (int i=0;i<8;i++)
    #pragma unroll
    for (int j=0;j<4;j++) acc[i][j]=0.f;

  for (int kt=0; kt<K; kt+=16){
    #pragma unroll
    for (int it=0; it<2; it++){
      int idx = tid + it*256;
      int row = idx >> 2, k4 = (idx & 3)*4;
      float4 v = *(const float4*)(A + (long)(m0+row)*K + kt + k4);
      As[k4+0][row]=v.x; As[k4+1][row]=v.y; As[k4+2][row]=v.z; As[k4+3][row]=v.w;
    }
    {
      int kb = tid >> 4, nb = (tid & 15)*4;
      float4 v = *(const float4*)(B + (long)(kt+kb)*HD + n0 + nb);
      *(float4*)&Bs[kb][nb] = v;
    }
    __syncthreads();
    #pragma unroll
    for (int kk=0;kk<16;kk++){
      float4 a0 = *(const float4*)&As[kk][ty*8];
      float4 a1 = *(const float4*)&As[kk][ty*8+4];
      float4 b4 = *(const float4*)&Bs[kk][tx*4];
      float a[8] = {a0.x,a0.y,a0.z,a0.w,a1.x,a1.y,a1.z,a1.w};
      float b[4] = {b4.x,b4.y,b4.z,b4.w};
      #pragma unroll
      for (int i=0;i<8;i++)
        #pragma unroll
        for (int j=0;j<4;j++) acc[i][j] += a[i]*b[j];
    }
    __syncthreads();
  }

  int col = n0 + tx*4;
  const float BNS = rsqrtf(1.0f + 1e-5f);
  float bv[4], gv[4], bev[4], lgv[4], lbv[4];
  #pragma unroll
  for (int j=0;j<4;j++) bv[j]=bias[col+j];
  if (EPI==EPI_RELU_BN || EPI==EPI_GIN){
    #pragma unroll
    for (int j=0;j<4;j++){ gv[j]=g[col+j]*BNS; bev[j]=be[col+j]; }
  }
  float mean=0.f, denom=1.f;
  if (EPI==EPI_RES){
    #pragma unroll
    for (int j=0;j<4;j++){ lgv[j]=lng[col+j]; lbv[j]=lnb[col+j]; }
    const float inv = 1.0f/((float)NN*(float)HD);
    float s0 = stats[0], s1 = stats[1];
    mean = s0*inv;
    float var = s1*inv - mean*mean;
    denom = sqrtf(fmaxf(var,0.f)) + 1e-5f;
  }
  #pragma unroll
  for (int i=0;i<8;i++){
    int row = m0 + ty*8 + i;
    float4 o;
    float ov[4];
    #pragma unroll
    for (int j=0;j<4;j++){
      float v = acc[i][j] + bv[j];
      if (EPI==EPI_RELU_BN){
        v = fmaxf(v,0.f)*gv[j] + bev[j];
      } else if (EPI==EPI_GIN){
        v = fmaxf(v,0.f)*gv[j] + bev[j];
        v = (v>0.f)? v : 0.2f*v;
      } else if (EPI==EPI_RES){
        float hv = hres[(long)row*HD + col + j];
        float ln = (hv-mean)/denom*lgv[j] + lbv[j];
        v = ln + v;
        v = (v>0.f)? v : 0.2f*v;
      } else if (EPI==EPI_TANH){
        v = tanhf(v);
      }
      ov[j]=v;
    }
    o.x=ov[0]; o.y=ov[1]; o.z=ov[2]; o.w=ov[3];
    *(float4*)&C[(long)row*HD + col] = o;
  }
}

// ---------------- GATv2: warp-per-node, online softmax, CSR ----------------
__global__ __launch_bounds__(256)
void gat_kernel(const float* __restrict__ xl, const float* __restrict__ xr,
                const int* __restrict__ indptr, const int* __restrict__ col,
                const float* __restrict__ att, const float* __restrict__ gbias,
                float* __restrict__ hout){
  __shared__ float attS[256];
  if (threadIdx.x < 256) attS[threadIdx.x] = att[threadIdx.x];
  __syncthreads();
  int w = (blockIdx.x*blockDim.x + threadIdx.x)>>5;
  int lane = threadIdx.x & 31;
  if (w >= NN) return;
  float xrv[8];
  #pragma unroll
  for (int k=0;k<8;k++) xrv[k] = xr[w*HD + k*32 + lane];
  float m[8], s[8];
  #pragma unroll
  for (int k=0;k<8;k++){ m[k]=-1e30f; s[k]=0.f; }
  int p0 = indptr[w], p1 = indptr[w+1];
  for (int j=p0;j<p1;j++){
    int u = col[j];
    float lg[8];
    #pragma unroll
    for (int k=0;k<8;k++){
      float v = xl[u*HD + k*32 + lane] + xrv[k];
      v = (v>0.f)? v : 0.2f*v;
      lg[k] = v * attS[k*32+lane];
    }
    #pragma unroll
    for (int off=16; off>0; off>>=1){
      #pragma unroll
      for (int k=0;k<8;k++) lg[k] += __shfl_xor_sync(0xffffffffu, lg[k], off);
    }
    #pragma unroll
    for (int k=0;k<8;k++){
      if (lg[k] > m[k]){
        s[k] = s[k]*__expf(m[k]-lg[k]) + 1.f;
        m[k] = lg[k];
      } else {
        s[k] += __expf(lg[k]-m[k]);
      }
    }
  }
  float sinv[8];
  #pragma unroll
  for (int k=0;k<8;k++) sinv[k] = 1.f/(s[k]+1e-16f);
  float acc[8];
  #pragma unroll
  for (int k=0;k<8;k++) acc[k]=0.f;
  for (int j=p0;j<p1;j++){
    int u = col[j];
    float xlu[8], lg[8];
    #pragma unroll
    for (int k=0;k<8;k++){
      xlu[k] = xl[u*HD + k*32 + lane];
      float v = xlu[k] + xrv[k];
      v = (v>0.f)? v : 0.2f*v;
      lg[k] = v * attS[k*32+lane];
    }
    #pragma unroll
    for (int off=16; off>0; off>>=1){
      #pragma unroll
      for (int k=0;k<8;k++) lg[k] += __shfl_xor_sync(0xffffffffu, lg[k], off);
    }
    #pragma unroll
    for (int k=0;k<8;k++) acc[k] += __expf(lg[k]-m[k])*sinv[k]*xlu[k];
  }
  #pragma unroll
  for (int k=0;k<8;k++) hout[w*HD + k*32 + lane] = acc[k] + gbias[k*32+lane];
}

// ---------------- GIN aggregation: tmp = h + sum_{in-edges} h[src] ----------------
__global__ __launch_bounds__(256)
void ginagg_kernel(const float* __restrict__ h, const int* __restrict__ indptr,
                   const int* __restrict__ col, float* __restrict__ tmp){
  int w = (blockIdx.x*blockDim.x + threadIdx.x)>>5;
  int lane = threadIdx.x & 31;
  if (w >= NN) return;
  float acc[8];
  #pragma unroll
  for (int k=0;k<8;k++) acc[k] = h[w*HD + k*32 + lane];
  int p0 = indptr[w], p1 = indptr[w+1];
  for (int j=p0;j<p1;j++){
    int u = col[j];
    #pragma unroll
    for (int k=0;k<8;k++) acc[k] += h[u*HD + k*32 + lane];
  }
  #pragma unroll
  for (int k=0;k<8;k++) tmp[w*HD + k*32 + lane] = acc[k];
}

// ---------------- global LayerNorm stats ----------------
__global__ void stats_kernel(const float* __restrict__ h, float* red){
  float s=0.f, q=0.f;
  for (long i = blockIdx.x*blockDim.x+threadIdx.x; i < (long)NN*HD; i += (long)gridDim.x*blockDim.x){
    float v=h[i]; s+=v; q+=v*v;
  }
  #pragma unroll
  for (int off=16; off>0; off>>=1){
    s += __shfl_xor_sync(0xffffffffu, s, off);
    q += __shfl_xor_sync(0xffffffffu, q, off);
  }
  __shared__ float ws[8][2];
  int wid = threadIdx.x>>5, lane = threadIdx.x&31;
  if (lane==0){ ws[wid][0]=s; ws[wid][1]=q; }
  __syncthreads();
  if (threadIdx.x==0){
    float ts=0.f, tq=0.f;
    for (int i=0;i<8;i++){ ts+=ws[i][0]; tq+=ws[i][1]; }
    atomicAdd(&red[0], ts);
    atomicAdd(&red[1], tq);
  }
}

// ---------------- pooling ----------------
__global__ __launch_bounds__(256)
void gate_kernel(const float* __restrict__ t, const float* __restrict__ W2,
                 const float* __restrict__ b2, float* __restrict__ gate){
  int w = (blockIdx.x*blockDim.x + threadIdx.x)>>5;
  int lane = threadIdx.x & 31;
  if (w >= NN) return;
  float a=0.f;
  #pragma unroll
  for (int k=0;k<8;k++) a += t[w*HD + k*32 + lane]*W2[k*32+lane];
  #pragma unroll
  for (int off=16; off>0; off>>=1) a += __shfl_xor_sync(0xffffffffu, a, off);
  if (lane==0) gate[w] = a + b2[0];
}

__global__ void bmax_kernel(const float* __restrict__ gate, const int* __restrict__ batch, float* gmax){
  __shared__ float smax[GG];
  int t = threadIdx.x;
  if (t < GG) smax[t] = -1e30f;
  __syncthreads();
  int v = blockIdx.x*blockDim.x + t;
  if (v < NN) atomicMaxF(&smax[batch[v]], gate[v]);
  __syncthreads();
  if (t < GG) atomicMaxF(&gmax[t], smax[t]);
}

__global__ void bsum_kernel(float* __restrict__ gate, const int* __restrict__ batch,
                            const float* __restrict__ gmax, float* gsum){
  __shared__ float ssum[GG];
  int t = threadIdx.x;
  if (t < GG) ssum[t] = 0.f;
  __syncthreads();
  int v = blockIdx.x*blockDim.x + t;
  if (v < NN){
    int b = batch[v];
    float e = __expf(gate[v]-gmax[b]);
    gate[v] = e;
    atomicAdd(&ssum[b], e);
  }
  __syncthreads();
  if (t < GG) atomicAdd(&gsum[t], ssum[t]);
}

__global__ __launch_bounds__(256)
void emb_kernel(const float* __restrict__ gate, const int* __restrict__ batch,
                const float* __restrict__ gsum, const float* __restrict__ h, float* __restrict__ emb){
  int w = (blockIdx.x*blockDim.x + threadIdx.x)>>5;
  int lane = threadIdx.x & 31;
  if (w >= NN) return;
  int b = batch[w];
  float c = gate[w]/(gsum[b]+1e-16f);
  #pragma unroll
  for (int k=0;k<8;k++) atomicAdd(&emb[b*HD + k*32 + lane], c*h[w*HD + k*32 + lane]);
}

// ---------------- label heads ----------------
__global__ __launch_bounds__(256)
void head_kernel(const float* __restrict__ emb, const float* __restrict__ W1,
                 const float* __restrict__ b1, const float* __restrict__ g,
                 const float* __restrict__ be, const float* __restrict__ W2,
                 const float* __restrict__ b2, float* __restrict__ out){
  __shared__ float embS[GG*HD];
  __shared__ float sred[GG];
  int o = blockIdx.x;
  int t = threadIdx.x;
  for (int i=t;i<GG*HD;i+=256) embS[i]=emb[i];
  if (t < GG) sred[t]=0.f;
  __syncthreads();
  float acc[GG];
  #pragma unroll
  for (int b=0;b<GG;b++) acc[b]=0.f;
  const float* w = W1 + (long)o*HD*256 + t;
  for (int d=0;d<HD;d++){
    float wv = w[(long)d*256];
    #pragma unroll
    for (int b=0;b<GG;b++) acc[b] += embS[b*HD+d]*wv;
  }
  const float BNS = rsqrtf(1.0f + 1e-5f);
  float bnscale = g[o*256+t]*BNS;
  float beta = be[o*256+t];
  float bb1 = b1[o*256+t];
  float w2 = W2[o*256+t];
  #pragma unroll
  for (int b=0;b<GG;b++){
    float z = acc[b]+bb1;
    float sv = z/(1.f+__expf(-z));      // silu
    float bnv = sv*bnscale + beta;
    atomicAdd(&sred[b], bnv*w2);
  }
  __syncthreads();
  if (t < GG) out[t*OO + o] = sred[t] + b2[o];
}

// ---------------- host launch ----------------
extern "C" void kernel_launch(void* const* d_in, const int* in_sizes, int n_in,
                              void* d_out, int out_size) {
  (void)in_sizes; (void)n_in; (void)out_size;
  const float* x      = (const float*)d_in[0];
  const int*   ei     = (const int*)  d_in[1];
  const int*   batch  = (const int*)  d_in[2];
  const float* fp_W   = (const float*)d_in[3];
  const float* fp_b   = (const float*)d_in[4];
  const float* fp_g   = (const float*)d_in[5];
  const float* fp_be  = (const float*)d_in[6];
  const float* gat_Wl = (const float*)d_in[7];
  const float* gat_bl = (const float*)d_in[8];
  const float* gat_Wr = (const float*)d_in[9];
  const float* gat_br = (const float*)d_in[10];
  const float* gat_att= (const float*)d_in[11];
  const float* gat_bias=(const float*)d_in[12];
  const float* gin_W  = (const float*)d_in[13];
  const float* gin_b  = (const float*)d_in[14];
  const float* gin_g  = (const float*)d_in[15];
  const float* gin_be = (const float*)d_in[16];
  const float* ln_g   = (const float*)d_in[17];
  const float* ln_b   = (const float*)d_in[18];
  const float* res_W  = (const float*)d_in[19];
  const float* res_b  = (const float*)d_in[20];
  const float* pool_W1= (const float*)d_in[21];
  const float* pool_b1= (const float*)d_in[22];
  const float* pool_W2= (const float*)d_in[23];
  const float* pool_b2= (const float*)d_in[24];
  const float* head_W1= (const float*)d_in[25];
  const float* head_b1= (const float*)d_in[26];
  const float* head_g = (const float*)d_in[27];
  const float* head_be= (const float*)d_in[28];
  const float* head_W2= (const float*)d_in[29];
  const float* head_b2= (const float*)d_in[30];

  float *h0,*h1,*xl,*xr,*red,*gate,*gmax,*gsum,*emb;
  int *degGat,*degGin,*ptrGat,*ptrGin,*curGat,*curGin,*colGat,*colGin;
  cudaGetSymbolAddress((void**)&h0, d_h0);
  cudaGetSymbolAddress((void**)&h1, d_h1);
  cudaGetSymbolAddress((void**)&xl, d_xl);
  cudaGetSymbolAddress((void**)&xr, d_xr);
  cudaGetSymbolAddress((void**)&red, d_red);
  cudaGetSymbolAddress((void**)&gate, d_gate);
  cudaGetSymbolAddress((void**)&gmax, d_gmax);
  cudaGetSymbolAddress((void**)&gsum, d_gsum);
  cudaGetSymbolAddress((void**)&emb, d_emb);
  cudaGetSymbolAddress((void**)&degGat, d_degGat);
  cudaGetSymbolAddress((void**)&degGin, d_degGin);
  cudaGetSymbolAddress((void**)&ptrGat, d_ptrGat);
  cudaGetSymbolAddress((void**)&ptrGin, d_ptrGin);
  cudaGetSymbolAddress((void**)&curGat, d_curGat);
  cudaGetSymbolAddress((void**)&curGin, d_curGin);
  cudaGetSymbolAddress((void**)&colGat, d_colGat);
  cudaGetSymbolAddress((void**)&colGin, d_colGin);

  init_kernel<<<(NN+255)/256, 256>>>(degGat, degGin, red, gmax, gsum, emb);
  hist_kernel<<<(EP+255)/256, 256>>>(ei, degGat, degGin);
  scan_kernel<<<1, 1024>>>(degGat, ptrGat, curGat);
  scan_kernel<<<1, 1024>>>(degGin, ptrGin, curGin);
  fill_kernel<<<(EP+255)/256, 256>>>(ei, curGat, colGat, curGin, colGin);

  dim3 gg(NN/128, HD/64);   // (125, 4)

  // feature projection: h0 = bn(relu(x @ fp_W + fp_b))
  gemm_kernel<EPI_RELU_BN><<<gg,256>>>(x, fp_W, fp_b, fp_g, fp_be,
                                       nullptr, nullptr, nullptr, nullptr, h0, DIN);

  float* cur = h0;
  float* alt = h1;
  for (int i=0;i<2;i++){
    const float* Wl = gat_Wl + (long)i*HD*HD;
    const float* bl = gat_bl + (long)i*HD;
    const float* Wr = gat_Wr + (long)i*HD*HD;
    const float* br = gat_br + (long)i*HD;
    const float* at = gat_att + (long)i*8*32;
    const float* gb = gat_bias + (long)i*HD;
    const float* gW = gin_W + (long)i*HD*HD;
    const float* gbi= gin_b + (long)i*HD;
    const float* ggm= gin_g + (long)i*HD;
    const float* gbe= gin_be + (long)i*HD;
    const float* lg = ln_g + (long)i*HD;
    const float* lb = ln_b + (long)i*HD;
    const float* rW = res_W + (long)i*HD*HD;
    const float* rb = res_b + (long)i*HD;

    gemm_kernel<EPI_BIAS><<<gg,256>>>(cur, Wl, bl, nullptr,nullptr,nullptr,nullptr,nullptr,nullptr, xl, HD);
    gemm_kernel<EPI_BIAS><<<gg,256>>>(cur, Wr, br, nullptr,nullptr,nullptr,nullptr,nullptr,nullptr, xr, HD);
    gat_kernel<<<NN/8, 256>>>(xl, xr, ptrGat, colGat, at, gb, alt);
    { float* t = cur; cur = alt; alt = t; }

    ginagg_kernel<<<NN/8, 256>>>(cur, ptrGin, colGin, xl);   // reuse xl as tmp
    gemm_kernel<EPI_GIN><<<gg,256>>>(xl, gW, gbi, ggm, gbe, nullptr,nullptr,nullptr,nullptr, alt, HD);
    { float* t = cur; cur = alt; alt = t; }

    stats_kernel<<<512, 256>>>(cur, red + 2*i);
    gemm_kernel<EPI_RES><<<gg,256>>>(cur, rW, rb, nullptr,nullptr, lg, lb, cur, red + 2*i, alt, HD);
    { float* t = cur; cur = alt; alt = t; }
  }

  // pooling
  gemm_kernel<EPI_TANH><<<gg,256>>>(cur, pool_W1, pool_b1, nullptr,nullptr,nullptr,nullptr,nullptr,nullptr, xl, HD);
  gate_kernel<<<NN/8, 256>>>(xl, pool_W2, pool_b2, gate);
  bmax_kernel<<<(NN+255)/256, 256>>>(gate, batch, gmax);
  bsum_kernel<<<(NN+255)/256, 256>>>(gate, batch, gmax, gsum);
  emb_kernel<<<NN/8, 256>>>(gate, batch, gsum, cur, emb);

  // label heads
  head_kernel<<<OO, 256>>>(emb, head_W1, head_b1, head_g, head_be, head_W2, head_b2, (float*)d_out);
}

// round 2
// speedup vs baseline: 1.6844x; 1.6844x over previous
#include <cuda_runtime.h>
#include <stdint.h>
#include <math.h>

#define NN 16000
#define EE 256000
#define EP (EE+NN)
#define DIN 1280
#define HD 256
#define GG 32
#define OO 64

// ---------------- device scratch (static, allocation-free) ----------------
__device__ float d_h0[NN*HD];
__device__ float d_h1[NN*HD];
__device__ float d_xl[NN*HD];
__device__ float d_xr[NN*HD];
__device__ float d_elog[(long)EP*8];
__device__ int   d_degGat[NN], d_degGin[NN];
__device__ int   d_ptrGat[NN+1], d_ptrGin[NN+1];
__device__ int   d_curGat[NN], d_curGin[NN];
__device__ int   d_colGat[EP], d_colGin[EE];
__device__ float d_red[4];
__device__ float d_gate[NN], d_gmax[GG], d_gsum[GG], d_emb[GG*HD];

__device__ __forceinline__ void atomicMaxF(float* addr, float v){
  if (v >= 0.f) atomicMax((int*)addr, __float_as_int(v));
  else          atomicMin((unsigned int*)addr, __float_as_uint(v));
}

__device__ __forceinline__ uint32_t cvt_tf32(float x){
  uint32_t u; asm("cvt.rna.tf32.f32 %0, %1;" : "=r"(u) : "f"(x)); return u;
}

// ---------------- init + CSR build ----------------
__global__ void init_kernel(int* degGat,int* degGin,float* red,float* gmax,float* gsum,float* emb){
  int i = blockIdx.x*blockDim.x+threadIdx.x;
  if (i < NN){ degGat[i]=0; degGin[i]=0; }
  if (i < 4)  red[i]=0.f;
  if (i < GG){ gmax[i]=-1e30f; gsum[i]=0.f; }
  if (i < GG*HD) emb[i]=0.f;
}

__global__ void hist_kernel(const int* __restrict__ ei, int* degGat, int* degGin){
  int e = blockIdx.x*blockDim.x+threadIdx.x;
  if (e >= EP) return;
  if (e < EE){
    int d = ei[EE+e];
    atomicAdd(&degGat[d],1);
    atomicAdd(&degGin[d],1);
  } else {
    atomicAdd(&degGat[e-EE],1);
  }
}

// one launch, 2 blocks: block 0 scans GAT degrees, block 1 scans GIN degrees
__global__ void scan2_kernel(const int* __restrict__ degA, int* ptrA, int* curA,
                             const int* __restrict__ degB, int* ptrB, int* curB){
  const int* deg = blockIdx.x ? degB : degA;
  int* indptr    = blockIdx.x ? ptrB : ptrA;
  int* cursor    = blockIdx.x ? curB : curA;
  __shared__ int sh[1024];
  int t = threadIdx.x;
  const int CH = (NN+1023)/1024;   // 16
  int st = t*CH;
  int sum = 0;
  for (int i=0;i<CH;i++){ int idx=st+i; if (idx<NN) sum += deg[idx]; }
  sh[t]=sum; __syncthreads();
  for (int off=1; off<1024; off<<=1){
    int add = (t>=off)? sh[t-off] : 0;
    __syncthreads();
    sh[t]+=add;
    __syncthreads();
  }
  int run = (t==0)? 0 : sh[t-1];
  for (int i=0;i<CH;i++){
    int idx=st+i;
    if (idx<NN){ indptr[idx]=run; cursor[idx]=run; run+=deg[idx]; }
  }
  if (t==1023) indptr[NN]=sh[1023];
}

__global__ void fill_kernel(const int* __restrict__ ei, int* curGat, int* colGat, int* curGin, int* colGin){
  int e = blockIdx.x*blockDim.x+threadIdx.x;
  if (e >= EP) return;
  if (e < EE){
    int s = ei[e], d = ei[EE+e];
    colGat[atomicAdd(&curGat[d],1)] = s;
    colGin[atomicAdd(&curGin[d],1)] = s;
  } else {
    int v = e-EE;
    colGat[atomicAdd(&curGat[v],1)] = v;
  }
}

// ---------------- tf32 tensor-core GEMM: C[M,256] = A[M,K] @ B[K,256] + epilogue ----------------
enum { EPI_BIAS=0, EPI_RELU_BN=1, EPI_GIN=2, EPI_RES=3, EPI_TANH=4 };

template<int EPI>
__global__ __launch_bounds__(256)
void gemm_tc(const float* __restrict__ A, const float* __restrict__ B,
             const float* __restrict__ bias,
             const float* __restrict__ g,   const float* __restrict__ be,
             const float* __restrict__ lng, const float* __restrict__ lnb,
             const float* __restrict__ hres,
             const float* __restrict__ stats,
             float* __restrict__ C, int K)
{
  __shared__ float As[128][20];   // [row][k], pad->bank(20*tg+tk) conflict-free frag loads
  __shared__ float Bs[16][72];    // [k][n],  pad->bank(8*tk+tg)  conflict-free frag loads
  int tid = threadIdx.x;
  int lane = tid & 31, w = tid >> 5;
  int warpM = (w & 3) * 32;
  int warpN = (w >> 2) * 32;
  int m0 = blockIdx.x * 128;
  int n0 = blockIdx.y * 64;
  int tg = lane >> 2, tk = lane & 3;

  float acc[2][4][4];
  #pragma unroll
  for (int i=0;i<2;i++)
    #pragma unroll
    for (int j=0;j<4;j++)
      #pragma unroll
      for (int r=0;r<4;r++) acc[i][j][r]=0.f;

  for (int kt=0; kt<K; kt+=16){
    // A tile: 128 rows x 16 k
    #pragma unroll
    for (int it=0; it<2; it++){
      int idx = tid + it*256;
      int row = idx >> 2;
      int k4 = (idx & 3) * 4;
      float4 v = *(const float4*)(A + (long)(m0+row)*K + kt + k4);
      As[row][k4+0] = __uint_as_float(cvt_tf32(v.x));
      As[row][k4+1] = __uint_as_float(cvt_tf32(v.y));
      As[row][k4+2] = __uint_as_float(cvt_tf32(v.z));
      As[row][k4+3] = __uint_as_float(cvt_tf32(v.w));
    }
    // B tile: 16 k x 64 n
    {
      int kr = tid >> 4, nb = (tid & 15)*4;
      float4 v = *(const float4*)(B + (long)(kt+kr)*HD + n0 + nb);
      float4 o;
      o.x = __uint_as_float(cvt_tf32(v.x));
      o.y = __uint_as_float(cvt_tf32(v.y));
      o.z = __uint_as_float(cvt_tf32(v.z));
      o.w = __uint_as_float(cvt_tf32(v.w));
      *(float4*)&Bs[kr][nb] = o;
    }
    __syncthreads();
    #pragma unroll
    for (int ks=0; ks<2; ks++){
      int k0 = ks*8;
      uint32_t a[2][4], b[4][2];
      #pragma unroll
      for (int i=0;i<2;i++){
        int r = warpM + i*16 + tg;
        a[i][0] = __float_as_uint(As[r  ][k0+tk  ]);
        a[i][1] = __float_as_uint(As[r+8][k0+tk  ]);
        a[i][2] = __float_as_uint(As[r  ][k0+tk+4]);
        a[i][3] = __float_as_uint(As[r+8][k0+tk+4]);
      }
      #pragma unroll
      for (int j=0;j<4;j++){
        int c = warpN + j*8 + tg;
        b[j][0] = __float_as_uint(Bs[k0+tk  ][c]);
        b[j][1] = __float_as_uint(Bs[k0+tk+4][c]);
      }
      #pragma unroll
      for (int i=0;i<2;i++)
        #pragma unroll
        for (int j=0;j<4;j++)
          asm volatile("mma.sync.aligned.m16n8k8.row.col.f32.tf32.tf32.f32 "
            "{%0,%1,%2,%3}, {%4,%5,%6,%7}, {%8,%9}, {%0,%1,%2,%3};"
            : "+f"(acc[i][j][0]), "+f"(acc[i][j][1]),
              "+f"(acc[i][j][2]), "+f"(acc[i][j][3])
            : "r"(a[i][0]), "r"(a[i][1]), "r"(a[i][2]), "r"(a[i][3]),
              "r"(b[j][0]), "r"(b[j][1]));
    }
    __syncthreads();
  }

  // ---- epilogue ----
  const float BNS = rsqrtf(1.0f + 1e-5f);
  float mean=0.f, rdenom=1.f;
  if (EPI==EPI_RES){
    const float inv = 1.0f/((float)NN*(float)HD);
    mean = stats[0]*inv;
    float var = stats[1]*inv - mean*mean;
    rdenom = 1.f/(sqrtf(fmaxf(var,0.f)) + 1e-5f);
  }
  #pragma unroll
  for (int j=0;j<4;j++){
    int col = n0 + warpN + j*8 + tk*2;
    float b0 = bias[col], b1 = bias[col+1];
    float g0=0.f,g1=0.f,e0=0.f,e1=0.f;
    if (EPI==EPI_RELU_BN || EPI==EPI_GIN){
      g0=g[col]*BNS; g1=g[col+1]*BNS; e0=be[col]; e1=be[col+1];
    }
    float lg0=0.f,lg1=0.f,lb0=0.f,lb1=0.f;
    if (EPI==EPI_RES){
      lg0=lng[col]; lg1=lng[col+1]; lb0=lnb[col]; lb1=lnb[col+1];
    }
    #pragma unroll
    for (int i=0;i<2;i++){
      #pragma unroll
      for (int h=0;h<2;h++){
        int row = m0 + warpM + i*16 + tg + h*8;
        float v0 = acc[i][j][h*2+0] + b0;
        float v1 = acc[i][j][h*2+1] + b1;
        if (EPI==EPI_RELU_BN){
          v0 = fmaxf(v0,0.f)*g0 + e0;
          v1 = fmaxf(v1,0.f)*g1 + e1;
        } else if (EPI==EPI_GIN){
          v0 = fmaxf(v0,0.f)*g0 + e0; v0 = (v0>0.f)? v0 : 0.2f*v0;
          v1 = fmaxf(v1,0.f)*g1 + e1; v1 = (v1>0.f)? v1 : 0.2f*v1;
        } else if (EPI==EPI_RES){
          float2 hv = *(const float2*)&hres[(long)row*HD + col];
          v0 += (hv.x-mean)*rdenom*lg0 + lb0;
          v1 += (hv.y-mean)*rdenom*lg1 + lb1;
          v0 = (v0>0.f)? v0 : 0.2f*v0;
          v1 = (v1>0.f)? v1 : 0.2f*v1;
        } else if (EPI==EPI_TANH){
          v0 = tanhf(v0); v1 = tanhf(v1);
        }
        *(float2*)&C[(long)row*HD + col] = make_float2(v0,v1);
      }
    }
  }
}

// ---------------- GATv2: warp-per-node, online softmax, CSR, logit cache ----------------
__global__ __launch_bounds__(256)
void gat_kernel(const float* __restrict__ xl, const float* __restrict__ xr,
                const int* __restrict__ indptr, const int* __restrict__ col,
                const float* __restrict__ att, const float* __restrict__ gbias,
                float* __restrict__ elog, float* __restrict__ hout){
  __shared__ float attS[256];
  if (threadIdx.x < 256) attS[threadIdx.x] = att[threadIdx.x];
  __syncthreads();
  int w = (blockIdx.x*blockDim.x + threadIdx.x)>>5;
  int lane = threadIdx.x & 31;
  if (w >= NN) return;
  float xrv[8];
  #pragma unroll
  for (int k=0;k<8;k++) xrv[k] = xr[w*HD + k*32 + lane];
  float m[8], s[8];
  #pragma unroll
  for (int k=0;k<8;k++){ m[k]=-1e30f; s[k]=0.f; }
  int p0 = indptr[w], p1 = indptr[w+1];
  // pass 1: logits + online max/sum; cache reduced logits
  for (int j=p0;j<p1;j++){
    int u = col[j];
    float lg[8];
    #pragma unroll
    for (int k=0;k<8;k++){
      float v = xl[u*HD + k*32 + lane] + xrv[k];
      v = (v>0.f)? v : 0.2f*v;
      lg[k] = v * attS[k*32+lane];
    }
    #pragma unroll
    for (int off=16; off>0; off>>=1){
      #pragma unroll
      for (int k=0;k<8;k++) lg[k] += __shfl_xor_sync(0xffffffffu, lg[k], off);
    }
    if (lane < 8){
      float v = lg[0];
      #pragma unroll
      for (int k=1;k<8;k++) if (lane==k) v = lg[k];
      elog[(long)j*8 + lane] = v;
    }
    #pragma unroll
    for (int k=0;k<8;k++){
      if (lg[k] > m[k]){
        s[k] = s[k]*__expf(m[k]-lg[k]) + 1.f;
        m[k] = lg[k];
      } else {
        s[k] += __expf(lg[k]-m[k]);
      }
    }
  }
  float sinv[8];
  #pragma unroll
  for (int k=0;k<8;k++) sinv[k] = 1.f/(s[k]+1e-16f);
  float acc[8];
  #pragma unroll
  for (int k=0;k<8;k++) acc[k]=0.f;
  // pass 2: weighted gather using cached logits (no shuffles)
  for (int j=p0;j<p1;j++){
    int u = col[j];
    #pragma unroll
    for (int k=0;k<8;k++){
      float lgk = elog[(long)j*8 + k];            // broadcast
      float coef = __expf(lgk - m[k]) * sinv[k];
      acc[k] += coef * xl[u*HD + k*32 + lane];
    }
  }
  #pragma unroll
  for (int k=0;k<8;k++) hout[w*HD + k*32 + lane] = acc[k] + gbias[k*32+lane];
}

// ---------------- GIN aggregation: tmp = h + sum_{in-edges} h[src] ----------------
__global__ __launch_bounds__(256)
void ginagg_kernel(const float* __restrict__ h, const int* __restrict__ indptr,
                   const int* __restrict__ col, float* __restrict__ tmp){
  int w = (blockIdx.x*blockDim.x + threadIdx.x)>>5;
  int lane = threadIdx.x & 31;
  if (w >= NN) return;
  float acc[8];
  #pragma unroll
  for (int k=0;k<8;k++) acc[k] = h[w*HD + k*32 + lane];
  int p0 = indptr[w], p1 = indptr[w+1];
  for (int j=p0;j<p1;j++){
    int u = col[j];
    #pragma unroll
    for (int k=0;k<8;k++) acc[k] += h[u*HD + k*32 + lane];
  }
  #pragma unroll
  for (int k=0;k<8;k++) tmp[w*HD + k*32 + lane] = acc[k];
}

// ---------------- global LayerNorm stats ----------------
__global__ void stats_kernel(const float* __restrict__ h, float* red){
  float s=0.f, q=0.f;
  for (long i = blockIdx.x*blockDim.x+threadIdx.x; i < (long)NN*HD; i += (long)gridDim.x*blockDim.x){
    float v=h[i]; s+=v; q+=v*v;
  }
  #pragma unroll
  for (int off=16; off>0; off>>=1){
    s += __shfl_xor_sync(0xffffffffu, s, off);
    q += __shfl_xor_sync(0xffffffffu, q, off);
  }
  __shared__ float ws[8][2];
  int wid = threadIdx.x>>5, lane = threadIdx.x&31;
  if (lane==0){ ws[wid][0]=s; ws[wid][1]=q; }
  __syncthreads();
  if (threadIdx.x==0){
    float ts=0.f, tq=0.f;
    for (int i=0;i<8;i++){ ts+=ws[i][0]; tq+=ws[i][1]; }
    atomicAdd(&red[0], ts);
    atomicAdd(&red[1], tq);
  }
}

// ---------------- pooling ----------------
__global__ __launch_bounds__(256)
void gate_kernel(const float* __restrict__ t, const float* __restrict__ W2,
                 const float* __restrict__ b2, float* __restrict__ gate){
  int w = (blockIdx.x*blockDim.x + threadIdx.x)>>5;
  int lane = threadIdx.x & 31;
  if (w >= NN) return;
  float a=0.f;
  #pragma unroll
  for (int k=0;k<8;k++) a += t[w*HD + k*32 + lane]*W2[k*32+lane];
  #pragma unroll
  for (int off=16; off>0; off>>=1) a += __shfl_xor_sync(0xffffffffu, a, off);
  if (lane==0) gate[w] = a + b2[0];
}

__global__ void bmax_kernel(const float* __restrict__ gate, const int* __restrict__ batch, float* gmax){
  __shared__ float smax[GG];
  int t = threadIdx.x;
  if (t < GG) smax[t] = -1e30f;
  __syncthreads();
  int v = blockIdx.x*blockDim.x + t;
  if (v < NN) atomicMaxF(&smax[batch[v]], gate[v]);
  __syncthreads();
  if (t < GG) atomicMaxF(&gmax[t], smax[t]);
}

__global__ void bsum_kernel(float* __restrict__ gate, const int* __restrict__ batch,
                            const float* __restrict__ gmax, float* gsum){
  __shared__ float ssum[GG];
  int t = threadIdx.x;
  if (t < GG) ssum[t] = 0.f;
  __syncthreads();
  int v = blockIdx.x*blockDim.x + t;
  if (v < NN){
    int b = batch[v];
    float e = __expf(gate[v]-gmax[b]);
    gate[v] = e;
    atomicAdd(&ssum[b], e);
  }
  __syncthreads();
  if (t < GG) atomicAdd(&gsum[t], ssum[t]);
}

__global__ __launch_bounds__(256)
void emb_kernel(const float* __restrict__ gate, const int* __restrict__ batch,
                const float* __restrict__ gsum, const float* __restrict__ h, float* __restrict__ emb){
  int w = (blockIdx.x*blockDim.x + threadIdx.x)>>5;
  int lane = threadIdx.x & 31;
  if (w >= NN) return;
  int b = batch[w];
  float c = gate[w]/(gsum[b]+1e-16f);
  #pragma unroll
  for (int k=0;k<8;k++) atomicAdd(&emb[b*HD + k*32 + lane], c*h[w*HD + k*32 + lane]);
}

// ---------------- label heads ----------------
__global__ __launch_bounds__(256)
void head_kernel(const float* __restrict__ emb, const float* __restrict__ W1,
                 const float* __restrict__ b1, const float* __restrict__ g,
                 const float* __restrict__ be, const float* __restrict__ W2,
                 const float* __restrict__ b2, float* __restrict__ out){
  __shared__ float embS[GG*HD];
  __shared__ float sred[GG];
  int o = blockIdx.x;
  int t = threadIdx.x;
  for (int i=t;i<GG*HD;i+=256) embS[i]=emb[i];
  if (t < GG) sred[t]=0.f;
  __syncthreads();
  float acc[GG];
  #pragma unroll
  for (int b=0;b<GG;b++) acc[b]=0.f;
  const float* w = W1 + (long)o*HD*256 + t;
  for (int d=0;d<HD;d++){
    float wv = w[(long)d*256];
    #pragma unroll
    for (int b=0;b<GG;b++) acc[b] += embS[b*HD+d]*wv;
  }
  const float BNS = rsqrtf(1.0f + 1e-5f);
  float bnscale = g[o*256+t]*BNS;
  float beta = be[o*256+t];
  float bb1 = b1[o*256+t];
  float w2 = W2[o*256+t];
  #pragma unroll
  for (int b=0;b<GG;b++){
    float z = acc[b]+bb1;
    float sv = z/(1.f+__expf(-z));      // silu
    float bnv = sv*bnscale + beta;
    atomicAdd(&sred[b], bnv*w2);
  }
  __syncthreads();
  if (t < GG) out[t*OO + o] = sred[t] + b2[o];
}

// ---------------- host launch ----------------
extern "C" void kernel_launch(void* const* d_in, const int* in_sizes, int n_in,
                              void* d_out, int out_size) {
  (void)in_sizes; (void)n_in; (void)out_size;
  const float* x      = (const float*)d_in[0];
  const int*   ei     = (const int*)  d_in[1];
  const int*   batch  = (const int*)  d_in[2];
  const float* fp_W   = (const float*)d_in[3];
  const float* fp_b   = (const float*)d_in[4];
  const float* fp_g   = (const float*)d_in[5];
  const float* fp_be  = (const float*)d_in[6];
  const float* gat_Wl = (const float*)d_in[7];
  const float* gat_bl = (const float*)d_in[8];
  const float* gat_Wr = (const float*)d_in[9];
  const float* gat_br = (const float*)d_in[10];
  const float* gat_att= (const float*)d_in[11];
  const float* gat_bias=(const float*)d_in[12];
  const float* gin_W  = (const float*)d_in[13];
  const float* gin_b  = (const float*)d_in[14];
  const float* gin_g  = (const float*)d_in[15];
  const float* gin_be = (const float*)d_in[16];
  const float* ln_g   = (const float*)d_in[17];
  const float* ln_b   = (const float*)d_in[18];
  const float* res_W  = (const float*)d_in[19];
  const float* res_b  = (const float*)d_in[20];
  const float* pool_W1= (const float*)d_in[21];
  const float* pool_b1= (const float*)d_in[22];
  const float* pool_W2= (const float*)d_in[23];
  const float* pool_b2= (const float*)d_in[24];
  const float* head_W1= (const float*)d_in[25];
  const float* head_b1= (const float*)d_in[26];
  const float* head_g = (const float*)d_in[27];
  const float* head_be= (const float*)d_in[28];
  const float* head_W2= (const float*)d_in[29];
  const float* head_b2= (const float*)d_in[30];

  float *h0,*h1,*xl,*xr,*elog,*red,*gate,*gmax,*gsum,*emb;
  int *degGat,*degGin,*ptrGat,*ptrGin,*curGat,*curGin,*colGat,*colGin;
  cudaGetSymbolAddress((void**)&h0, d_h0);
  cudaGetSymbolAddress((void**)&h1, d_h1);
  cudaGetSymbolAddress((void**)&xl, d_xl);
  cudaGetSymbolAddress((void**)&xr, d_xr);
  cudaGetSymbolAddress((void**)&elog, d_elog);
  cudaGetSymbolAddress((void**)&red, d_red);
  cudaGetSymbolAddress((void**)&gate, d_gate);
  cudaGetSymbolAddress((void**)&gmax, d_gmax);
  cudaGetSymbolAddress((void**)&gsum, d_gsum);
  cudaGetSymbolAddress((void**)&emb, d_emb);
  cudaGetSymbolAddress((void**)&degGat, d_degGat);
  cudaGetSymbolAddress((void**)&degGin, d_degGin);
  cudaGetSymbolAddress((void**)&ptrGat, d_ptrGat);
  cudaGetSymbolAddress((void**)&ptrGin, d_ptrGin);
  cudaGetSymbolAddress((void**)&curGat, d_curGat);
  cudaGetSymbolAddress((void**)&curGin, d_curGin);
  cudaGetSymbolAddress((void**)&colGat, d_colGat);
  cudaGetSymbolAddress((void**)&colGin, d_colGin);

  init_kernel<<<(NN+255)/256, 256>>>(degGat, degGin, red, gmax, gsum, emb);
  hist_kernel<<<(EP+255)/256, 256>>>(ei, degGat, degGin);
  scan2_kernel<<<2, 1024>>>(degGat, ptrGat, curGat, degGin, ptrGin, curGin);
  fill_kernel<<<(EP+255)/256, 256>>>(ei, curGat, colGat, curGin, colGin);

  dim3 gg(NN/128, HD/64);   // (125, 4)

  // feature projection: h0 = bn(relu(x @ fp_W + fp_b))
  gemm_tc<EPI_RELU_BN><<<gg,256>>>(x, fp_W, fp_b, fp_g, fp_be,
                                   nullptr, nullptr, nullptr, nullptr, h0, DIN);

  float* cur = h0;
  float* alt = h1;
  for (int i=0;i<2;i++){
    const float* Wl = gat_Wl + (long)i*HD*HD;
    const float* bl = gat_bl + (long)i*HD;
    const float* Wr = gat_Wr + (long)i*HD*HD;
    const float* br = gat_br + (long)i*HD;
    const float* at = gat_att + (long)i*8*32;
    const float* gb = gat_bias + (long)i*HD;
    const float* gW = gin_W + (long)i*HD*HD;
    const float* gbi= gin_b + (long)i*HD;
    const float* ggm= gin_g + (long)i*HD;
    const float* gbe= gin_be + (long)i*HD;
    const float* lg = ln_g + (long)i*HD;
    const float* lb = ln_b + (long)i*HD;
    const float* rW = res_W + (long)i*HD*HD;
    const float* rb = res_b + (long)i*HD;

    gemm_tc<EPI_BIAS><<<gg,256>>>(cur, Wl, bl, nullptr,nullptr,nullptr,nullptr,nullptr,nullptr, xl, HD);
    gemm_tc<EPI_BIAS><<<gg,256>>>(cur, Wr, br, nullptr,nullptr,nullptr,nullptr,nullptr,nullptr, xr, HD);
    gat_kernel<<<NN/8, 256>>>(xl, xr, ptrGat, colGat, at, gb, elog, alt);
    { float* t = cur; cur = alt; alt = t; }

    ginagg_kernel<<<NN/8, 256>>>(cur, ptrGin, colGin, xl);   // reuse xl as tmp
    gemm_tc<EPI_GIN><<<gg,256>>>(xl, gW, gbi, ggm, gbe, nullptr,nullptr,nullptr,nullptr, alt, HD);
    { float* t = cur; cur = alt; alt = t; }

    stats_kernel<<<512, 256>>>(cur, red + 2*i);
    gemm_tc<EPI_RES><<<gg,256>>>(cur, rW, rb, nullptr,nullptr, lg, lb, cur, red + 2*i, alt, HD);
    { float* t = cur; cur = alt; alt = t; }
  }

  // pooling
  gemm_tc<EPI_TANH><<<gg,256>>>(cur, pool_W1, pool_b1, nullptr,nullptr,nullptr,nullptr,nullptr,nullptr, xl, HD);
  gate_kernel<<<NN/8, 256>>>(xl, pool_W2, pool_b2, gate);
  bmax_kernel<<<(NN+255)/256, 256>>>(gate, batch, gmax);
  bsum_kernel<<<(NN+255)/256, 256>>>(gate, batch, gmax, gsum);
  emb_kernel<<<NN/8, 256>>>(gate, batch, gsum, cur, emb);

  // label heads
  head_kernel<<<OO, 256>>>(emb, head_W1, head_b1, head_g, head_be, head_W2, head_b2, (float*)d_out);
}